// round 1
// baseline (speedup 1.0000x reference)
#include <cuda_runtime.h>
#include <math.h>

// Problem constants
#define B 32
#define S 2048
#define D 1024
#define MASK_PENALTY 100000000.0f

// Tiling
#define NSPLIT 8                      // S-splits per batch
#define WARPS 8                       // warps per CTA
#define THREADS (WARPS * 32)
#define ROWS_PER_SPLIT (S / NSPLIT)   // 256
#define ROWS_PER_WARP (ROWS_PER_SPLIT / WARPS)  // 32
#define NPART (NSPLIT * WARPS)        // 64 partials per batch

// Scratch for partials (allocation-free: __device__ globals)
__device__ float g_m[B * NPART];
__device__ float g_l[B * NPART];
__device__ float g_acc[(size_t)B * NPART * D];

// ---------------------------------------------------------------------------
// Pass 1: single-pass online-softmax attention over an S-split.
// One warp per context row; each lane owns 32 of the 1024 D-elements,
// laid out as 8 float4 with element offset 4*(lane + 32*i)  (coalesced).
// ---------------------------------------------------------------------------
__global__ void __launch_bounds__(THREADS)
attn_pass1(const float* __restrict__ target,
           const float* __restrict__ context,
           const float* __restrict__ mask)
{
    const int b     = blockIdx.x;
    const int split = blockIdx.y;
    const int w     = threadIdx.x >> 5;
    const int lane  = threadIdx.x & 31;

    // Load this lane's slice of the query vector
    const float4* tg = (const float4*)(target + (size_t)b * D);
    float4 t[8];
#pragma unroll
    for (int i = 0; i < 8; i++) t[i] = tg[lane + 32 * i];

    float4 acc[8];
#pragma unroll
    for (int i = 0; i < 8; i++) acc[i] = make_float4(0.f, 0.f, 0.f, 0.f);

    float m = -INFINITY;
    float l = 0.f;

    const int s0 = split * ROWS_PER_SPLIT + w * ROWS_PER_WARP;
    const float* cb = context + (size_t)b * S * D;
    const float* mk = mask + (size_t)b * S;

    for (int r = 0; r < ROWS_PER_WARP; r++) {
        const int s = s0 + r;
        const float4* row = (const float4*)(cb + (size_t)s * D);

        float4 c[8];
#pragma unroll
        for (int i = 0; i < 8; i++) c[i] = row[lane + 32 * i];

        // dot(context_row, target) for this lane's slice
        float dot = 0.f;
#pragma unroll
        for (int i = 0; i < 8; i++) {
            dot = fmaf(c[i].x, t[i].x, dot);
            dot = fmaf(c[i].y, t[i].y, dot);
            dot = fmaf(c[i].z, t[i].z, dot);
            dot = fmaf(c[i].w, t[i].w, dot);
        }
        // warp reduce (butterfly -> all lanes hold the full dot)
#pragma unroll
        for (int off = 16; off > 0; off >>= 1)
            dot += __shfl_xor_sync(0xffffffffu, dot, off);

        const float score = dot + (mk[s] - 1.f) * MASK_PENALTY;

        // online softmax update
        const float mnew  = fmaxf(m, score);
        const float scale = __expf(m - mnew);     // 0 on first iter (m = -inf)
        const float wgt   = __expf(score - mnew);
        l = l * scale + wgt;
#pragma unroll
        for (int i = 0; i < 8; i++) {
            acc[i].x = fmaf(acc[i].x, scale, wgt * c[i].x);
            acc[i].y = fmaf(acc[i].y, scale, wgt * c[i].y);
            acc[i].z = fmaf(acc[i].z, scale, wgt * c[i].z);
            acc[i].w = fmaf(acc[i].w, scale, wgt * c[i].w);
        }
        m = mnew;
    }

    // Write this warp's partial
    const int pidx = (b * NSPLIT + split) * WARPS + w;
    if (lane == 0) {
        g_m[pidx] = m;
        g_l[pidx] = l;
    }
    float4* ga = (float4*)(g_acc + (size_t)pidx * D);
#pragma unroll
    for (int i = 0; i < 8; i++) ga[lane + 32 * i] = acc[i];
}

// ---------------------------------------------------------------------------
// Pass 2: merge the 64 partials per batch.
// out[b,d] = sum_p exp(m_p - M) * acc_p[d] / sum_p exp(m_p - M) * l_p
// ---------------------------------------------------------------------------
__global__ void __launch_bounds__(256)
attn_pass2(float* __restrict__ out)
{
    const int b = blockIdx.x;
    __shared__ float sM, sLinv;

    if (threadIdx.x == 0) {
        float M = -INFINITY;
#pragma unroll 4
        for (int p = 0; p < NPART; p++)
            M = fmaxf(M, g_m[b * NPART + p]);
        float L = 0.f;
#pragma unroll 4
        for (int p = 0; p < NPART; p++)
            L += __expf(g_m[b * NPART + p] - M) * g_l[b * NPART + p];
        sM = M;
        sLinv = 1.f / L;
    }
    __syncthreads();

    const float M = sM;
    const float Linv = sLinv;
    const int d4 = threadIdx.x;  // 256 threads x float4 = 1024 elements

    float4 a = make_float4(0.f, 0.f, 0.f, 0.f);
    for (int p = 0; p < NPART; p++) {
        const float f = __expf(g_m[b * NPART + p] - M);
        const float4 v =
            ((const float4*)(g_acc + ((size_t)(b * NPART + p)) * D))[d4];
        a.x = fmaf(f, v.x, a.x);
        a.y = fmaf(f, v.y, a.y);
        a.z = fmaf(f, v.z, a.z);
        a.w = fmaf(f, v.w, a.w);
    }
    a.x *= Linv; a.y *= Linv; a.z *= Linv; a.w *= Linv;
    ((float4*)(out + (size_t)b * D))[d4] = a;
}

extern "C" void kernel_launch(void* const* d_in, const int* in_sizes, int n_in,
                              void* d_out, int out_size)
{
    const float* target  = (const float*)d_in[0];  // [B, D]
    const float* context = (const float*)d_in[1];  // [B, S, D]
    const float* mask    = (const float*)d_in[2];  // [B, S]
    float* out = (float*)d_out;                    // [B, D]

    dim3 grid1(B, NSPLIT);
    attn_pass1<<<grid1, THREADS>>>(target, context, mask);
    attn_pass2<<<B, 256>>>(out);
}

// round 2
// speedup vs baseline: 1.2482x; 1.2482x over previous
#include <cuda_runtime.h>
#include <math.h>

// Problem constants
#define B 32
#define S 2048
#define D 1024
#define MASK_PENALTY 100000000.0f

// Tiling
#define NSPLIT 8                      // S-splits per batch -> 8 partials/batch
#define WARPS 8                       // warps per CTA
#define THREADS (WARPS * 32)
#define ROWS_PER_SPLIT (S / NSPLIT)   // 256
#define ROWS_PER_WARP (ROWS_PER_SPLIT / WARPS)  // 32

// Scratch for per-CTA partials (allocation-free: __device__ globals)
__device__ float g_m[B * NSPLIT];
__device__ float g_l[B * NSPLIT];
__device__ float g_acc[(size_t)B * NSPLIT * D];   // 1 MB

// ---------------------------------------------------------------------------
// Pass 1: single-pass online-softmax attention over an S-split.
// One warp per context row; each lane owns 32 of the 1024 D-elements
// (8 x float4 at element offset 4*(lane + 32*i), fully coalesced).
// The 8 warps' partials are merged in shared memory -> ONE partial per CTA.
// ---------------------------------------------------------------------------
__global__ void __launch_bounds__(THREADS)
attn_pass1(const float* __restrict__ target,
           const float* __restrict__ context,
           const float* __restrict__ mask)
{
    const int b     = blockIdx.x;
    const int split = blockIdx.y;
    const int w     = threadIdx.x >> 5;
    const int lane  = threadIdx.x & 31;

    // Lane's slice of the query vector
    const float4* tg = (const float4*)(target + (size_t)b * D);
    float4 t[8];
#pragma unroll
    for (int i = 0; i < 8; i++) t[i] = tg[lane + 32 * i];

    float4 acc[8];
#pragma unroll
    for (int i = 0; i < 8; i++) acc[i] = make_float4(0.f, 0.f, 0.f, 0.f);

    float m = -INFINITY;
    float l = 0.f;

    const int s0 = split * ROWS_PER_SPLIT + w * ROWS_PER_WARP;
    const float* cb = context + (size_t)b * S * D;
    const float* mk = mask + (size_t)b * S;

    for (int r = 0; r < ROWS_PER_WARP; r++) {
        const int s = s0 + r;
        const float4* row = (const float4*)(cb + (size_t)s * D);

        float4 c[8];
#pragma unroll
        for (int i = 0; i < 8; i++) c[i] = row[lane + 32 * i];

        float dot = 0.f;
#pragma unroll
        for (int i = 0; i < 8; i++) {
            dot = fmaf(c[i].x, t[i].x, dot);
            dot = fmaf(c[i].y, t[i].y, dot);
            dot = fmaf(c[i].z, t[i].z, dot);
            dot = fmaf(c[i].w, t[i].w, dot);
        }
#pragma unroll
        for (int off = 16; off > 0; off >>= 1)
            dot += __shfl_xor_sync(0xffffffffu, dot, off);

        const float score = dot + (mk[s] - 1.f) * MASK_PENALTY;

        const float mnew  = fmaxf(m, score);
        const float scale = __expf(m - mnew);
        const float wgt   = __expf(score - mnew);
        l = l * scale + wgt;
#pragma unroll
        for (int i = 0; i < 8; i++) {
            acc[i].x = fmaf(acc[i].x, scale, wgt * c[i].x);
            acc[i].y = fmaf(acc[i].y, scale, wgt * c[i].y);
            acc[i].z = fmaf(acc[i].z, scale, wgt * c[i].z);
            acc[i].w = fmaf(acc[i].w, scale, wgt * c[i].w);
        }
        m = mnew;
    }

    // ---- In-CTA merge of the 8 warp partials ----
    __shared__ float sm[WARPS];
    __shared__ float sl[WARPS];
    __shared__ float4 sacc[WARPS][D / 4];   // 32 KB

    if (lane == 0) { sm[w] = m; sl[w] = l; }
    __syncthreads();

    float Mcta = -INFINITY;
#pragma unroll
    for (int i = 0; i < WARPS; i++) Mcta = fmaxf(Mcta, sm[i]);

    // scale this warp's acc into smem
    const float f = __expf(m - Mcta);
#pragma unroll
    for (int i = 0; i < 8; i++) {
        float4 a = acc[i];
        a.x *= f; a.y *= f; a.z *= f; a.w *= f;
        sacc[w][lane + 32 * i] = a;
    }
    __syncthreads();

    // 256 threads sum across the 8 warps
    const int pidx = b * NSPLIT + split;
    const int d4 = threadIdx.x;   // 0..255
    float4 sum = sacc[0][d4];
#pragma unroll
    for (int i = 1; i < WARPS; i++) {
        const float4 v = sacc[i][d4];
        sum.x += v.x; sum.y += v.y; sum.z += v.z; sum.w += v.w;
    }
    ((float4*)(g_acc + (size_t)pidx * D))[d4] = sum;

    if (threadIdx.x == 0) {
        float L = 0.f;
#pragma unroll
        for (int i = 0; i < WARPS; i++)
            L += __expf(sm[i] - Mcta) * sl[i];
        g_m[pidx] = Mcta;
        g_l[pidx] = L;
    }
}

// ---------------------------------------------------------------------------
// Pass 2: merge the 8 partials per batch. grid = (B, 4), 64 threads.
// Each thread handles one float4 of the output; per-thread M/L recompute
// (8 scalar loads, L2-resident) avoids any synchronization.
// ---------------------------------------------------------------------------
__global__ void __launch_bounds__(64)
attn_pass2(float* __restrict__ out)
{
    const int b  = blockIdx.x;
    const int d4 = blockIdx.y * 64 + threadIdx.x;   // 0..255

    float pm[NSPLIT], pl[NSPLIT];
#pragma unroll
    for (int p = 0; p < NSPLIT; p++) {
        pm[p] = g_m[b * NSPLIT + p];
        pl[p] = g_l[b * NSPLIT + p];
    }
    float M = -INFINITY;
#pragma unroll
    for (int p = 0; p < NSPLIT; p++) M = fmaxf(M, pm[p]);
    float L = 0.f;
#pragma unroll
    for (int p = 0; p < NSPLIT; p++) L += __expf(pm[p] - M) * pl[p];
    const float Linv = 1.f / L;

    float4 a = make_float4(0.f, 0.f, 0.f, 0.f);
#pragma unroll
    for (int p = 0; p < NSPLIT; p++) {
        const float f = __expf(pm[p] - M);
        const float4 v =
            ((const float4*)(g_acc + (size_t)(b * NSPLIT + p) * D))[d4];
        a.x = fmaf(f, v.x, a.x);
        a.y = fmaf(f, v.y, a.y);
        a.z = fmaf(f, v.z, a.z);
        a.w = fmaf(f, v.w, a.w);
    }
    a.x *= Linv; a.y *= Linv; a.z *= Linv; a.w *= Linv;
    ((float4*)(out + (size_t)b * D))[d4] = a;
}

extern "C" void kernel_launch(void* const* d_in, const int* in_sizes, int n_in,
                              void* d_out, int out_size)
{
    const float* target  = (const float*)d_in[0];  // [B, D]
    const float* context = (const float*)d_in[1];  // [B, S, D]
    const float* mask    = (const float*)d_in[2];  // [B, S]
    float* out = (float*)d_out;                    // [B, D]

    dim3 grid1(B, NSPLIT);
    attn_pass1<<<grid1, THREADS>>>(target, context, mask);
    dim3 grid2(B, 4);
    attn_pass2<<<grid2, 64>>>(out);
}